// round 2
// baseline (speedup 1.0000x reference)
#include <cuda_runtime.h>
#include <cstdint>

#define N_NODES  400000
#define N_EDGES  1600000
#define N_GRAPHS 16384
#define HID      64

// ---------------- scratch (device globals; no allocation allowed) -----------
__device__ __align__(128) float g_agg[(size_t)N_NODES * HID];   // GEMM input
__device__ __align__(128) float g_h  [(size_t)N_NODES * HID];   // GEMM output (post relu)
__device__ int   g_cnt[N_NODES];
__device__ int   g_rowptr[N_NODES + 1];
__device__ int   g_cur[N_NODES];
__device__ int   g_col[N_EDGES];
__device__ float g_dinv[N_NODES];
__device__ int   g_part[512];
__device__ __align__(128) float g_fused[(size_t)N_GRAPHS * 208];

// ---------------- f32x2 helpers ---------------------------------------------
__device__ __forceinline__ unsigned long long pack2(float a, float b) {
    unsigned long long r;
    asm("mov.b64 %0, {%1, %2};" : "=l"(r) : "f"(a), "f"(b));
    return r;
}
__device__ __forceinline__ void unpack2(unsigned long long v, float& a, float& b) {
    asm("mov.b64 {%0, %1}, %2;" : "=f"(a), "=f"(b) : "l"(v));
}
__device__ __forceinline__ void fma2(unsigned long long& d,
                                     unsigned long long a, unsigned long long b) {
    asm("fma.rn.f32x2 %0, %1, %2, %0;" : "+l"(d) : "l"(a), "l"(b));
}

// ---------------- structure build -------------------------------------------
__global__ void k_zero_cnt() {
    int i = blockIdx.x * blockDim.x + threadIdx.x;
    if (i < N_NODES) g_cnt[i] = 0;
}

__global__ void k_hist(const int* __restrict__ row) {
    int e = blockIdx.x * blockDim.x + threadIdx.x;
    if (e < N_EDGES) atomicAdd(&g_cnt[row[e]], 1);
}

__global__ void k_dinv() {
    int i = blockIdx.x * blockDim.x + threadIdx.x;
    if (i < N_NODES) g_dinv[i] = rsqrtf((float)g_cnt[i] + 1.0f);
}

// scan phase A: 1024 elems / block (256 thr x 4), local exclusive scan + block sums
__global__ void k_scan_a() {
    __shared__ int ws[8];
    int tid = threadIdx.x;
    int base = blockIdx.x * 1024 + tid * 4;
    int v0 = (base + 0 < N_NODES) ? g_cnt[base + 0] : 0;
    int v1 = (base + 1 < N_NODES) ? g_cnt[base + 1] : 0;
    int v2 = (base + 2 < N_NODES) ? g_cnt[base + 2] : 0;
    int v3 = (base + 3 < N_NODES) ? g_cnt[base + 3] : 0;
    int t = v0 + v1 + v2 + v3;
    int lane = tid & 31, w = tid >> 5;
    int incl = t;
#pragma unroll
    for (int o = 1; o < 32; o <<= 1) {
        int u = __shfl_up_sync(0xffffffffu, incl, o);
        if (lane >= o) incl += u;
    }
    if (lane == 31) ws[w] = incl;
    __syncthreads();
    if (tid < 32) {
        int val = (tid < 8) ? ws[tid] : 0;
        int inc2 = val;
#pragma unroll
        for (int o = 1; o < 8; o <<= 1) {
            int u = __shfl_up_sync(0xffffffffu, inc2, o);
            if (tid >= o) inc2 += u;
        }
        if (tid < 8) ws[tid] = inc2 - val;      // exclusive warp offsets
        if (tid == 7) g_part[blockIdx.x] = inc2; // block total
    }
    __syncthreads();
    int off = ws[w] + (incl - t);
    if (base + 0 < N_NODES) g_rowptr[base + 0] = off; off += v0;
    if (base + 1 < N_NODES) g_rowptr[base + 1] = off; off += v1;
    if (base + 2 < N_NODES) g_rowptr[base + 2] = off; off += v2;
    if (base + 3 < N_NODES) g_rowptr[base + 3] = off;
}

// scan phase B: single block exclusive scan of block sums (nb <= 512)
__global__ void k_scan_b(int nb) {
    __shared__ int s[512];
    int tid = threadIdx.x;
    int v = (tid < nb) ? g_part[tid] : 0;
    s[tid] = v;
    __syncthreads();
    for (int o = 1; o < 512; o <<= 1) {
        int add = (tid >= o) ? s[tid - o] : 0;
        __syncthreads();
        s[tid] += add;
        __syncthreads();
    }
    if (tid < nb) g_part[tid] = s[tid] - v;
}

// scan phase C: add block offsets, copy to scatter cursors, set rowptr[N]
__global__ void k_scan_c() {
    int i = blockIdx.x * blockDim.x + threadIdx.x;
    if (i < N_NODES) {
        int r = g_rowptr[i] + g_part[i >> 10];
        g_rowptr[i] = r;
        g_cur[i] = r;
    }
    if (i == 0) g_rowptr[N_NODES] = N_EDGES;
}

__global__ void k_scatter(const int* __restrict__ row, const int* __restrict__ col) {
    int e = blockIdx.x * blockDim.x + threadIdx.x;
    if (e < N_EDGES) {
        int r = row[e];
        int p = atomicAdd(&g_cur[r], 1);
        g_col[p] = col[e];
    }
}

// ---------------- aggregation: out[i] = dinv_i*(dinv_i*in[i] + sum dinv_c*in[c])
// warp per node; D=32 reads external x, D=64 reads g_h
__global__ void k_agg32(const float* __restrict__ x) {
    int gid = blockIdx.x * blockDim.x + threadIdx.x;
    int node = gid >> 5;
    if (node >= N_NODES) return;
    int lane = gid & 31;
    float di = g_dinv[node];
    float acc = di * x[node * 32 + lane];
    int e = g_rowptr[node], end = g_rowptr[node + 1];
    for (; e + 2 <= end; e += 2) {
        int c0 = g_col[e], c1 = g_col[e + 1];
        float w0 = g_dinv[c0], w1 = g_dinv[c1];
        float u0 = x[c0 * 32 + lane], u1 = x[c1 * 32 + lane];
        acc = fmaf(w0, u0, acc);
        acc = fmaf(w1, u1, acc);
    }
    if (e < end) {
        int c = g_col[e];
        acc = fmaf(g_dinv[c], x[c * 32 + lane], acc);
    }
    g_agg[node * 32 + lane] = di * acc;
}

__global__ void k_agg64() {
    int gid = blockIdx.x * blockDim.x + threadIdx.x;
    int node = gid >> 5;
    if (node >= N_NODES) return;
    int lane = gid & 31;
    const float2* h2 = (const float2*)g_h;
    float di = g_dinv[node];
    float2 s = h2[node * 32 + lane];
    float ax = di * s.x, ay = di * s.y;
    int e = g_rowptr[node], end = g_rowptr[node + 1];
    for (; e + 2 <= end; e += 2) {
        int c0 = g_col[e], c1 = g_col[e + 1];
        float w0 = g_dinv[c0], w1 = g_dinv[c1];
        float2 u0 = h2[c0 * 32 + lane], u1 = h2[c1 * 32 + lane];
        ax = fmaf(w0, u0.x, ax); ay = fmaf(w0, u0.y, ay);
        ax = fmaf(w1, u1.x, ax); ay = fmaf(w1, u1.y, ay);
    }
    if (e < end) {
        int c = g_col[e];
        float w = g_dinv[c];
        float2 u = h2[c * 32 + lane];
        ax = fmaf(w, u.x, ax); ay = fmaf(w, u.y, ay);
    }
    ((float2*)g_agg)[node * 32 + lane] = make_float2(di * ax, di * ay);
}

// ---------------- GEMM: g_h = relu(g_agg[N,K] @ W[K,64] + b), f32x2 packed ----
template <int K>
__global__ void __launch_bounds__(128) k_gemm(const float* __restrict__ W,
                                              const float* __restrict__ bias) {
    __shared__ __align__(16) float sW[K * 64];
    __shared__ float sB[64];
    int tid = threadIdx.x;
    for (int i = tid; i < K * 64; i += 128) sW[i] = W[i];
    if (tid < 64) sB[tid] = bias[tid];
    __syncthreads();

    int r0 = blockIdx.x * 256 + tid;
    int r1 = r0 + 128;
    bool v0 = r0 < N_NODES, v1 = r1 < N_NODES;
    const float4* p0 = (const float4*)g_agg + (size_t)r0 * (K / 4);
    const float4* p1 = (const float4*)g_agg + (size_t)r1 * (K / 4);

    unsigned long long acc0[32], acc1[32];
#pragma unroll
    for (int j = 0; j < 32; j++) { acc0[j] = 0ull; acc1[j] = 0ull; }

    const ulonglong2* w2 = (const ulonglong2*)sW;
#pragma unroll
    for (int k4 = 0; k4 < K / 4; k4++) {
        float4 a0 = v0 ? p0[k4] : make_float4(0.f, 0.f, 0.f, 0.f);
        float4 a1 = v1 ? p1[k4] : make_float4(0.f, 0.f, 0.f, 0.f);
        float a0a[4] = {a0.x, a0.y, a0.z, a0.w};
        float a1a[4] = {a1.x, a1.y, a1.z, a1.w};
#pragma unroll
        for (int kk = 0; kk < 4; kk++) {
            int k = k4 * 4 + kk;
            unsigned long long pa0 = pack2(a0a[kk], a0a[kk]);
            unsigned long long pa1 = pack2(a1a[kk], a1a[kk]);
#pragma unroll
            for (int j4 = 0; j4 < 16; j4++) {
                ulonglong2 w = w2[k * 16 + j4];
                fma2(acc0[2 * j4],     pa0, w.x);
                fma2(acc0[2 * j4 + 1], pa0, w.y);
                fma2(acc1[2 * j4],     pa1, w.x);
                fma2(acc1[2 * j4 + 1], pa1, w.y);
            }
        }
    }
    if (v0) {
        float4* o = (float4*)g_h + (size_t)r0 * 16;
#pragma unroll
        for (int j4 = 0; j4 < 16; j4++) {
            float x0, x1, x2, x3;
            unpack2(acc0[2 * j4], x0, x1);
            unpack2(acc0[2 * j4 + 1], x2, x3);
            float4 r;
            r.x = fmaxf(x0 + sB[4 * j4 + 0], 0.f);
            r.y = fmaxf(x1 + sB[4 * j4 + 1], 0.f);
            r.z = fmaxf(x2 + sB[4 * j4 + 2], 0.f);
            r.w = fmaxf(x3 + sB[4 * j4 + 3], 0.f);
            o[j4] = r;
        }
    }
    if (v1) {
        float4* o = (float4*)g_h + (size_t)r1 * 16;
#pragma unroll
        for (int j4 = 0; j4 < 16; j4++) {
            float x0, x1, x2, x3;
            unpack2(acc1[2 * j4], x0, x1);
            unpack2(acc1[2 * j4 + 1], x2, x3);
            float4 r;
            r.x = fmaxf(x0 + sB[4 * j4 + 0], 0.f);
            r.y = fmaxf(x1 + sB[4 * j4 + 1], 0.f);
            r.z = fmaxf(x2 + sB[4 * j4 + 2], 0.f);
            r.w = fmaxf(x3 + sB[4 * j4 + 3], 0.f);
            o[j4] = r;
        }
    }
}

// ---------------- pooling: warp per graph (batch is sorted) ------------------
__device__ __forceinline__ int lower_bound_dev(const int* __restrict__ a, int n, int key) {
    int lo = 0, hi = n;
    while (lo < hi) {
        int m = (lo + hi) >> 1;
        if (a[m] < key) lo = m + 1; else hi = m;
    }
    return lo;
}

__global__ void k_pool(const int* __restrict__ batch) {
    int gid = blockIdx.x * blockDim.x + threadIdx.x;
    int g = gid >> 5;
    if (g >= N_GRAPHS) return;
    int lane = gid & 31;
    int s = lower_bound_dev(batch, N_NODES, g);
    int e = lower_bound_dev(batch, N_NODES, g + 1);
    const float2* h2 = (const float2*)g_h;
    float sx = 0.f, sy = 0.f, mx = 0.f, my = 0.f;  // relu output >= 0, so 0-init max is exact
    for (int n = s; n < e; n++) {
        float2 v = h2[n * 32 + lane];
        sx += v.x; sy += v.y;
        mx = fmaxf(mx, v.x); my = fmaxf(my, v.y);
    }
    float inv = 1.f / (float)((e - s) > 0 ? (e - s) : 1);
    float2* f = (float2*)(g_fused + (size_t)g * 208);
    f[lane]      = make_float2(sx * inv, sy * inv);
    f[32 + lane] = make_float2(mx, my);
}

// ---------------- meta encoder + species embedding ---------------------------
__global__ void k_meta(const float* __restrict__ metadata,
                       const float* __restrict__ Wm, const float* __restrict__ bm,
                       const float* __restrict__ semb, const int* __restrict__ species) {
    int idx = blockIdx.x * blockDim.x + threadIdx.x;
    if (idx >= N_GRAPHS * 64) return;
    int g = idx >> 6, j = idx & 63;
    const float* mrow = metadata + g * 16;
    float acc = bm[j];
#pragma unroll
    for (int k = 0; k < 16; k++) acc = fmaf(mrow[k], Wm[k * 64 + j], acc);
    g_fused[(size_t)g * 208 + 128 + j] = fmaxf(acc, 0.f);
    if (j < 16) {
        int sid = species[g];
        g_fused[(size_t)g * 208 + 192 + j] = semb[sid * 16 + j];
    }
}

// ---------------- predictor: out = relu(fused @ Wp1 + bp1) @ Wp2 + bp2 -------
__global__ void k_pred(const float* __restrict__ Wp1, const float* __restrict__ bp1,
                       const float* __restrict__ Wp2, const float* __restrict__ bp2,
                       float* __restrict__ out) {
    __shared__ float sF[4][208];
    __shared__ float red[8];
    int tid = threadIdx.x;
    int gbase = blockIdx.x * 4;
    for (int i = tid; i < 4 * 208; i += 256) {
        int gl = i / 208, k = i % 208;
        sF[gl][k] = g_fused[(size_t)(gbase + gl) * 208 + k];
    }
    __syncthreads();
    int gl = tid >> 6, j = tid & 63;
    float acc = bp1[j];
#pragma unroll 8
    for (int k = 0; k < 208; k++) acc = fmaf(sF[gl][k], Wp1[k * 64 + j], acc);
    float v = fmaxf(acc, 0.f) * Wp2[j];
#pragma unroll
    for (int o = 16; o > 0; o >>= 1) v += __shfl_down_sync(0xffffffffu, v, o);
    if ((tid & 31) == 0) red[tid >> 5] = v;
    __syncthreads();
    if (tid < 4) out[gbase + tid] = red[2 * tid] + red[2 * tid + 1] + bp2[0];
}

// ---------------- launch -----------------------------------------------------
extern "C" void kernel_launch(void* const* d_in, const int* in_sizes, int n_in,
                              void* d_out, int out_size) {
    const float* x        = (const float*)d_in[0];
    const float* metadata = (const float*)d_in[1];
    const int*   edge     = (const int*)d_in[2];
    const int*   batch    = (const int*)d_in[3];
    const int*   species  = (const int*)d_in[4];
    const float* W1 = (const float*)d_in[5];
    const float* b1 = (const float*)d_in[6];
    const float* W2 = (const float*)d_in[7];
    const float* b2 = (const float*)d_in[8];
    const float* W3 = (const float*)d_in[9];
    const float* b3 = (const float*)d_in[10];
    const float* Wm = (const float*)d_in[11];
    const float* bm = (const float*)d_in[12];
    const float* semb = (const float*)d_in[13];
    const float* Wp1  = (const float*)d_in[14];
    const float* bp1  = (const float*)d_in[15];
    const float* Wp2  = (const float*)d_in[16];
    const float* bp2  = (const float*)d_in[17];
    float* out = (float*)d_out;

    const int* row = edge;
    const int* col = edge + N_EDGES;

    const int NB_N   = (N_NODES + 255) / 256;          // 1563
    const int NB_E   = (N_EDGES + 255) / 256;          // 6250
    const int NB_SC  = (N_NODES + 1023) / 1024;        // 391
    const int NB_AGG = (N_NODES * 32) / 256;           // 50000
    const int NB_GM  = (N_NODES + 255) / 256;          // 1563 (256 rows/block)

    // structure build
    k_zero_cnt<<<NB_N, 256>>>();
    k_hist<<<NB_E, 256>>>(row);
    k_dinv<<<NB_N, 256>>>();
    k_scan_a<<<NB_SC, 256>>>();
    k_scan_b<<<1, 512>>>(NB_SC);
    k_scan_c<<<NB_N, 256>>>();
    k_scatter<<<NB_E, 256>>>(row, col);

    // layer 1 (aggregate 32-dim x first, then GEMM)
    k_agg32<<<NB_AGG, 256>>>(x);
    k_gemm<32><<<NB_GM, 128>>>(W1, b1);
    // layer 2
    k_agg64<<<NB_AGG, 256>>>();
    k_gemm<64><<<NB_GM, 128>>>(W2, b2);
    // layer 3
    k_agg64<<<NB_AGG, 256>>>();
    k_gemm<64><<<NB_GM, 128>>>(W3, b3);

    // pooling + head
    k_pool<<<(N_GRAPHS * 32) / 256, 256>>>(batch);
    k_meta<<<(N_GRAPHS * 64) / 256, 256>>>(metadata, Wm, bm, semb, species);
    k_pred<<<N_GRAPHS / 4, 256>>>(Wp1, bp1, Wp2, bp2, out);
}